// round 10
// baseline (speedup 1.0000x reference)
#include <cuda_runtime.h>
#include <math.h>

#define BATCH  64
#define LSUB   512
#define SWORDS 512
#define HID    768
#define NC     9
#define NWORDS (BATCH * SWORDS)
#define NSM    148
#define SLOTS  8
#define ROWB   (HID * 4)               // 3072 bytes per row
#define SLOT_BYTES (3 * ROWB)          // 9216
#define STAGE_BYTES (SLOTS * SLOT_BYTES)  // 73728
#define DYN_BYTES (2 * STAGE_BYTES)    // 147456

typedef unsigned long long u64;

__device__ float g_Wt[NC * HID];
__device__ int   g_ls[NWORDS];         // (start<<2)|len
__device__ int   g_nv[BATCH];
__device__ int   g_widx[NWORDS];       // compacted valid word ids
__device__ int   g_total;
__device__ float g_loss;
__device__ int   g_cnt;
__device__ int   g_done;

__device__ __forceinline__ u64 fma2(u64 a, u64 b, u64 c) {
    u64 d; asm("fma.rn.f32x2 %0,%1,%2,%3;" : "=l"(d) : "l"(a), "l"(b), "l"(c)); return d;
}
__device__ __forceinline__ u64 add2(u64 a, u64 b) {
    u64 d; asm("add.rn.f32x2 %0,%1,%2;" : "=l"(d) : "l"(a), "l"(b)); return d;
}
__device__ __forceinline__ float upk_sum(u64 v) {
    float lo, hi; asm("mov.b64 {%0,%1},%2;" : "=f"(lo), "=f"(hi) : "l"(v)); return lo + hi;
}
__device__ __forceinline__ void cpa16(unsigned dst, const void* src) {
    asm volatile("cp.async.cg.shared.global [%0], [%1], 16;" :: "r"(dst), "l"(src));
}
#define CP_COMMIT() asm volatile("cp.async.commit_group;" ::: "memory")
#define CP_WAIT1()  asm volatile("cp.async.wait_group 1;" ::: "memory")

// ---------------------------------------------------------------------------
// Setup1: per-batch scan -> g_ls, valid counts -> g_nv, W transpose,
// default preds (= argmax(bias)), reset accumulators.
// ---------------------------------------------------------------------------
__global__ void __launch_bounds__(256) setup1_kernel(
    const int* __restrict__ ids_lens, const float* __restrict__ W,
    const float* __restrict__ bias, float* __restrict__ out)
{
    __shared__ int s_wsum[8];
    __shared__ int s_vcnt[8];
    const int b = blockIdx.x, tid = threadIdx.x;
    const int lane = tid & 31, warp = tid >> 5;

    int2 lp = ((const int2*)(ids_lens + b * SWORDS))[tid];
    int sum2 = lp.x + lp.y;
    int inc = sum2;
#pragma unroll
    for (int off = 1; off < 32; off <<= 1) {
        int n = __shfl_up_sync(0xffffffffu, inc, off);
        if (lane >= off) inc += n;
    }
    int lane_ex = inc - sum2;
    int vc = (lp.x > 0) + (lp.y > 0);
#pragma unroll
    for (int off = 16; off; off >>= 1) vc += __shfl_xor_sync(0xffffffffu, vc, off);
    if (lane == 31) s_wsum[warp] = inc;
    if (lane == 0)  s_vcnt[warp] = vc;
    __syncthreads();
    int wbase = 0;
#pragma unroll
    for (int i = 0; i < 8; i++) if (i < warp) wbase += s_wsum[i];
    int ex0 = wbase + lane_ex;
    int base = b * SWORDS + 2 * tid;
    g_ls[base]     = (ex0 << 2) | lp.x;
    g_ls[base + 1] = ((ex0 + lp.x) << 2) | lp.y;

    {
        float m = -1e30f; int am = 0;
#pragma unroll
        for (int c = 0; c < NC; c++) { float v = bias[c]; if (v > m) { m = v; am = c; } }
        out[1 + base] = (float)am; out[1 + base + 1] = (float)am;
    }
    if (tid < 12 * NC) {
        int h = b * 12 + tid / NC;
        int c = tid - (tid / NC) * NC;
        g_Wt[c * HID + h] = W[h * NC + c];
    }
    if (tid == 0) {
        int tot = 0;
#pragma unroll
        for (int i = 0; i < 8; i++) tot += s_vcnt[i];
        g_nv[b] = tot;
        if (b == 0) { g_loss = 0.0f; g_cnt = 0; g_done = 0; }
    }
}

// ---------------------------------------------------------------------------
// Setup2: cross-batch compaction. Block b writes its valid word ids into
// g_widx at its global offset. Block 0 also writes g_total.
// ---------------------------------------------------------------------------
__global__ void __launch_bounds__(256) setup2_kernel(const int* __restrict__ ids_lens)
{
    __shared__ int s_nv[BATCH];
    __shared__ int s_wsum[8];
    const int b = blockIdx.x, tid = threadIdx.x;
    const int lane = tid & 31, warp = tid >> 5;

    if (tid < BATCH) s_nv[tid] = g_nv[tid];
    __syncthreads();
    int off_b = 0, tot = 0;
    for (int i = 0; i < BATCH; i++) { if (i < b) off_b += s_nv[i]; tot += s_nv[i]; }
    if (b == 0 && tid == 0) g_total = tot;

    int2 lp = ((const int2*)(ids_lens + b * SWORDS))[tid];
    int f0 = (lp.x > 0), f1 = (lp.y > 0);
    int sum2 = f0 + f1;
    int inc = sum2;
#pragma unroll
    for (int off = 1; off < 32; off <<= 1) {
        int n = __shfl_up_sync(0xffffffffu, inc, off);
        if (lane >= off) inc += n;
    }
    int lane_ex = inc - sum2;
    if (lane == 31) s_wsum[warp] = inc;
    __syncthreads();
    int wbase = 0;
#pragma unroll
    for (int i = 0; i < 8; i++) if (i < warp) wbase += s_wsum[i];
    int pos = off_b + wbase + lane_ex;
    int w = b * SWORDS + 2 * tid;
    if (f0) g_widx[pos] = w;
    if (f1) g_widx[pos + f0] = w + 1;
}

// ---------------------------------------------------------------------------
// Main: 148 persistent blocks, double-buffered cp.async staging of 8 valid
// words per step; warps 0-3 compute word-pairs from shared.
// ---------------------------------------------------------------------------
__global__ void __launch_bounds__(256) main_kernel(
    const float* __restrict__ x,
    const float* __restrict__ bias,
    const int*   __restrict__ label_ids,
    float*       __restrict__ out)
{
    extern __shared__ char dbuf[];            // 2 stages of SLOTS*9216B
    __shared__ float Ws[NC * HID];
    __shared__ float sb[NC];
    __shared__ int   s_mw[2][SLOTS];
    __shared__ int   s_mlen[2][SLOTS];
    __shared__ float s_loss;
    __shared__ int   s_cnt;

    const int tid  = threadIdx.x;
    const int lane = tid & 31;
    const int warp = tid >> 5;

    {
        const float4* src = (const float4*)g_Wt;
        float4*       dst = (float4*)Ws;
        for (int i = tid; i < (NC * HID) / 4; i += 256) dst[i] = src[i];
    }
    if (tid < NC) sb[tid] = bias[tid];
    if (tid == 0) { s_loss = 0.0f; s_cnt = 0; }

    const int total = g_total;
    const unsigned dyn_u32 = (unsigned)__cvta_generic_to_shared(dbuf);

    // ---- stage lambda: warp q stages slot q of 'step' into buffer bi ----
    auto stage = [&](int step, int bi) {
        int j = step * SLOTS + warp;
        int w = -1, len = 0, st = 0, batch = 0;
        if (step >= 0 && j < total) {
            w = g_widx[j];
            int ls = g_ls[w];
            len = ls & 3; st = ls >> 2; batch = w >> 9;
        }
        if (lane == 0) { s_mw[bi][warp] = w; s_mlen[bi][warp] = len; }
        const char* src = (const char*)(x + ((size_t)(batch * LSUB + st)) * HID);
        unsigned dst = dyn_u32 + bi * STAGE_BYTES + warp * SLOT_BYTES;
        for (int r = 0; r < len; r++) {
#pragma unroll
            for (int k = 0; k < 6; k++) {
                int o = r * ROWB + (k * 32 + lane) * 16;
                cpa16(dst + o, src + o);
            }
        }
    };

    // prologue: stage step = blockIdx.x into buffer 0
    stage(blockIdx.x, 0);
    CP_COMMIT();

    float lloss = 0.0f;
    int   lcnt  = 0;
    const ulonglong2 z2 = make_ulonglong2(0ull, 0ull);

    int i = 0;
#pragma unroll 1
    for (;;) {
        int step = blockIdx.x + NSM * i;
        if (step * SLOTS >= total) break;
        int bi = i & 1;

        // stage next step into the other buffer (may be empty)
        stage(blockIdx.x + NSM * (i + 1), bi ^ 1);
        CP_COMMIT();
        CP_WAIT1();                           // current buffer landed
        __syncthreads();

        if (warp < 4) {
            int q0 = 2 * warp, q1 = q0 + 1;
            int w0 = s_mw[bi][q0], w1 = s_mw[bi][q1];
            int len0 = s_mlen[bi][q0], len1 = s_mlen[bi][q1];
            const char* p0 = dbuf + bi * STAGE_BYTES + q0 * SLOT_BYTES;
            const char* p1 = dbuf + bi * STAGE_BYTES + q1 * SLOT_BYTES;

            u64 acc0[NC], acc1[NC];
#pragma unroll
            for (int c = 0; c < NC; c++) { acc0[c] = 0ull; acc1[c] = 0ull; }

#pragma unroll
            for (int g = 0; g < 6; g++) {
                int o = (g * 32 + lane) * 16;
                ulonglong2 a0 = (len0 > 0) ? *(const ulonglong2*)(p0 + o)            : z2;
                ulonglong2 a1 = (len0 > 1) ? *(const ulonglong2*)(p0 + ROWB + o)     : z2;
                ulonglong2 a2 = (len0 > 2) ? *(const ulonglong2*)(p0 + 2 * ROWB + o) : z2;
                ulonglong2 c0 = (len1 > 0) ? *(const ulonglong2*)(p1 + o)            : z2;
                ulonglong2 c1 = (len1 > 1) ? *(const ulonglong2*)(p1 + ROWB + o)     : z2;
                ulonglong2 c2 = (len1 > 2) ? *(const ulonglong2*)(p1 + 2 * ROWB + o) : z2;

                u64 v0l = add2(a0.x, add2(a1.x, a2.x));
                u64 v0h = add2(a0.y, add2(a1.y, a2.y));
                u64 v1l = add2(c0.x, add2(c1.x, c2.x));
                u64 v1h = add2(c0.y, add2(c1.y, c2.y));

                int hb = g * 128 + lane * 4;
#pragma unroll
                for (int c = 0; c < NC; c++) {
                    ulonglong2 wc = *(const ulonglong2*)&Ws[c * HID + hb];
                    acc0[c] = fma2(v0l, wc.x, acc0[c]);
                    acc0[c] = fma2(v0h, wc.y, acc0[c]);
                    acc1[c] = fma2(v1l, wc.x, acc1[c]);
                    acc1[c] = fma2(v1h, wc.y, acc1[c]);
                }
            }

            float r0[NC], r1[NC];
#pragma unroll
            for (int c = 0; c < NC; c++) { r0[c] = upk_sum(acc0[c]); r1[c] = upk_sum(acc1[c]); }
#pragma unroll
            for (int c = 0; c < NC; c++) {
#pragma unroll
                for (int off = 16; off; off >>= 1) {
                    r0[c] += __shfl_xor_sync(0xffffffffu, r0[c], off);
                    r1[c] += __shfl_xor_sync(0xffffffffu, r1[c], off);
                }
            }

            if (lane == 0) {
#pragma unroll
                for (int which = 0; which < 2; which++) {
                    int    w   = which ? w1 : w0;
                    int    len = which ? len1 : len0;
                    float* a   = which ? r1 : r0;
                    if (w < 0 || len == 0) continue;

                    float inv = 1.0f / (float)len;
                    float lg[NC];
                    float m = -1e30f; int am = 0;
#pragma unroll
                    for (int c = 0; c < NC; c++) {
                        lg[c] = fmaf(a[c], inv, sb[c]);
                        if (lg[c] > m) { m = lg[c]; am = c; }
                    }
                    out[1 + w] = (float)am;
                    float sum = 0.0f;
#pragma unroll
                    for (int c = 0; c < NC; c++) sum += __expf(lg[c] - m);
                    int lab = label_ids[w];
                    lab = lab < 0 ? 0 : (lab > NC - 1 ? NC - 1 : lab);
                    lloss += -(lg[lab] - m - __logf(sum));
                    lcnt  += 1;
                }
            }
        }
        __syncthreads();                       // readers done before re-staging
        i++;
    }

    if (warp < 4 && lane == 0 && lcnt > 0) {
        atomicAdd(&s_loss, lloss);
        atomicAdd(&s_cnt, lcnt);
    }
    __syncthreads();
    if (tid == 0) {
        if (s_cnt > 0) {
            atomicAdd(&g_loss, s_loss);
            atomicAdd(&g_cnt, s_cnt);
        }
        __threadfence();
        int old = atomicAdd(&g_done, 1);
        if (old == NSM - 1) {
            float lv = atomicAdd(&g_loss, 0.0f);
            int   cv = atomicAdd(&g_cnt, 0);
            out[0] = lv / fmaxf((float)cv, 1.0f);
        }
    }
}

extern "C" void kernel_launch(void* const* d_in, const int* in_sizes, int n_in,
                              void* d_out, int out_size) {
    const float* bert_out  = (const float*)d_in[0];
    const float* W         = (const float*)d_in[1];
    const float* b         = (const float*)d_in[2];
    const int*   ids_lens  = (const int*)d_in[4];
    const int*   label_ids = (const int*)d_in[5];
    float* out = (float*)d_out;

    cudaFuncSetAttribute(main_kernel, cudaFuncAttributeMaxDynamicSharedMemorySize, DYN_BYTES);

    setup1_kernel<<<BATCH, 256>>>(ids_lens, W, b, out);
    setup2_kernel<<<BATCH, 256>>>(ids_lens);
    main_kernel<<<NSM, 256, DYN_BYTES>>>(bert_out, b, label_ids, out);
}

// round 11
// speedup vs baseline: 1.7128x; 1.7128x over previous
#include <cuda_runtime.h>
#include <math.h>

#define BATCH  64
#define LSUB   512
#define SWORDS 512
#define HID    768
#define NC     9
#define NWORDS (BATCH * SWORDS)
#define MGRID  296          // 2 blocks/SM, one wave

typedef unsigned long long u64;

__device__ float g_Wt[NC * HID];
__device__ int   g_ls[NWORDS];         // (start<<2)|len
__device__ int   g_widx[NWORDS];       // compacted valid word ids (any order)
__device__ int   g_total;
__device__ int   g_alloc;              // zero-init; self-cleaned
__device__ int   g_done0;              // zero-init; self-cleaned
__device__ float g_loss;               // zero-init; self-cleaned by main
__device__ int   g_cnt;
__device__ int   g_done;

__device__ __forceinline__ u64 fma2(u64 a, u64 b, u64 c) {
    u64 d; asm("fma.rn.f32x2 %0,%1,%2,%3;" : "=l"(d) : "l"(a), "l"(b), "l"(c)); return d;
}
__device__ __forceinline__ u64 add2(u64 a, u64 b) {
    u64 d; asm("add.rn.f32x2 %0,%1,%2;" : "=l"(d) : "l"(a), "l"(b)); return d;
}
__device__ __forceinline__ float upk_sum(u64 v) {
    float lo, hi; asm("mov.b64 {%0,%1},%2;" : "=f"(lo), "=f"(hi) : "l"(v)); return lo + hi;
}

// ---------------------------------------------------------------------------
// Setup: 64 blocks x 256 threads. Block b: dual scan (subword starts + valid
// count, packed in one int), writes g_ls, compacts valid ids into g_widx via
// atomicAdd block offset, W transpose slice, default preds, counter cleanup.
// ---------------------------------------------------------------------------
__global__ void __launch_bounds__(256) setup_kernel(
    const int* __restrict__ ids_lens, const float* __restrict__ W,
    const float* __restrict__ bias, float* __restrict__ out)
{
    __shared__ int s_comb[8];
    __shared__ int s_off;
    const int b = blockIdx.x, tid = threadIdx.x;
    const int lane = tid & 31, warp = tid >> 5;

    int2 lp = ((const int2*)(ids_lens + b * SWORDS))[tid];
    int f0 = (lp.x > 0), f1 = (lp.y > 0);
    int comb = ((lp.x + lp.y) << 16) | (f0 + f1);   // packed: lens | validcnt
    int inc = comb;
#pragma unroll
    for (int off = 1; off < 32; off <<= 1) {
        int n = __shfl_up_sync(0xffffffffu, inc, off);
        if (lane >= off) inc += n;
    }
    int lane_ex = inc - comb;
    if (lane == 31) s_comb[warp] = inc;
    __syncthreads();
    int wbase = 0;
#pragma unroll
    for (int i = 0; i < 8; i++) if (i < warp) wbase += s_comb[i];
    int ex = wbase + lane_ex;
    int st0 = ex >> 16;
    int vx  = ex & 0xffff;

    const int base = b * SWORDS + 2 * tid;
    g_ls[base]     = (st0 << 2) | lp.x;
    g_ls[base + 1] = ((st0 + lp.x) << 2) | lp.y;

    if (tid == 0) {
        int t = 0;
#pragma unroll
        for (int i = 0; i < 8; i++) t += s_comb[i];
        s_off = atomicAdd(&g_alloc, t & 0xffff);
    }
    __syncthreads();
    int pos = s_off + vx;
    if (f0) g_widx[pos]      = base;
    if (f1) g_widx[pos + f0] = base + 1;

    // default preds = argmax(bias)
    {
        float m = -1e30f; int am = 0;
#pragma unroll
        for (int c = 0; c < NC; c++) { float v = bias[c]; if (v > m) { m = v; am = c; } }
        out[1 + base] = (float)am; out[1 + base + 1] = (float)am;
    }
    if (tid < 12 * NC) {
        int h = b * 12 + tid / NC;
        int c = tid - (tid / NC) * NC;
        g_Wt[c * HID + h] = W[h * NC + c];
    }
    if (tid == 0) {
        __threadfence();
        int old = atomicAdd(&g_done0, 1);
        if (old == BATCH - 1) {               // last setup block
            g_total = atomicAdd(&g_alloc, 0);
            atomicExch(&g_alloc, 0);          // self-clean for next replay
            atomicExch(&g_done0, 0);
        }
    }
}

// ---------------------------------------------------------------------------
// Main: 296 blocks x 256 threads. Pairs of valid words from g_widx (int2),
// metadata prefetched one iteration ahead, f32x2 dot vs W in shared,
// split 45-shfl reduce, two-lane parallel epilogue.
// ---------------------------------------------------------------------------
__global__ void __launch_bounds__(256, 2) main_kernel(
    const float* __restrict__ x,
    const float* __restrict__ bias,
    const int*   __restrict__ label_ids,
    float*       __restrict__ out)
{
    __shared__ float Ws[NC * HID];
    __shared__ float sb[NC];
    __shared__ float s_loss;
    __shared__ int   s_cnt;

    const int tid  = threadIdx.x;
    const int lane = tid & 31;
    const int warp = tid >> 5;

    {
        const float4* src = (const float4*)g_Wt;
        float4*       dst = (float4*)Ws;
        for (int i = tid; i < (NC * HID) / 4; i += 256) dst[i] = src[i];
    }
    if (tid < NC) sb[tid] = bias[tid];
    if (tid == 0) { s_loss = 0.0f; s_cnt = 0; }
    __syncthreads();

    const int total  = g_total;
    const int npairs = (total + 1) >> 1;
    const int gw = blockIdx.x * 8 + warp;
    const int nw = MGRID * 8;

    float lloss = 0.0f;
    int   lcnt  = 0;

    const ulonglong2 z2 = make_ulonglong2(0ull, 0ull);
    const int RS = HID / 4;

    const int2* widx2 = (const int2*)g_widx;

    int p = gw;
    int2 wp = make_int2(0, 0);
    int lsa = 0, lsb = 0;
    if (p < npairs) {
        wp  = widx2[p];
        lsa = g_ls[wp.x];
        lsb = g_ls[wp.y];
    }

#pragma unroll 1
    while (p < npairs) {
        // prefetch next iteration's metadata
        int pn = p + nw;
        int2 wpn = wp; int lsan = lsa, lsbn = lsb;
        if (pn < npairs) {
            wpn  = widx2[pn];
            lsan = g_ls[wpn.x];
            lsbn = g_ls[wpn.y];
        }

        int w0 = wp.x, w1 = wp.y;
        bool act1 = (2 * p + 1 < total);
        int len0 = lsa & 3, len1 = lsb & 3;
        int st0  = lsa >> 2, st1 = lsb >> 2;
        int b0 = w0 >> 9, b1 = w1 >> 9;

        const ulonglong2* base0 = (const ulonglong2*)(x + ((size_t)(b0 * LSUB + st0)) * HID);
        const ulonglong2* base1 = (const ulonglong2*)(x + ((size_t)(b1 * LSUB + st1)) * HID);

        u64 acc0[NC], acc1[NC];
#pragma unroll
        for (int c = 0; c < NC; c++) { acc0[c] = 0ull; acc1[c] = 0ull; }

#pragma unroll
        for (int g = 0; g < 6; g++) {
            int idx = g * 32 + lane;
            ulonglong2 a0 = (len0 > 0) ? base0[idx]          : z2;
            ulonglong2 a1 = (len0 > 1) ? base0[idx + RS]     : z2;
            ulonglong2 a2 = (len0 > 2) ? base0[idx + 2 * RS] : z2;
            ulonglong2 c0 = (len1 > 0) ? base1[idx]          : z2;
            ulonglong2 c1 = (len1 > 1) ? base1[idx + RS]     : z2;
            ulonglong2 c2 = (len1 > 2) ? base1[idx + 2 * RS] : z2;

            u64 v0l = add2(a0.x, add2(a1.x, a2.x));
            u64 v0h = add2(a0.y, add2(a1.y, a2.y));
            u64 v1l = add2(c0.x, add2(c1.x, c2.x));
            u64 v1h = add2(c0.y, add2(c1.y, c2.y));

            int hb = g * 128 + lane * 4;
#pragma unroll
            for (int c = 0; c < NC; c++) {
                ulonglong2 wc = *(const ulonglong2*)&Ws[c * HID + hb];
                acc0[c] = fma2(v0l, wc.x, acc0[c]);
                acc0[c] = fma2(v0h, wc.y, acc0[c]);
                acc1[c] = fma2(v1l, wc.x, acc1[c]);
                acc1[c] = fma2(v1h, wc.y, acc1[c]);
            }
        }

        // split reduce: level 16 routes word0 -> lanes 0-15, word1 -> 16-31
        float v[NC];
#pragma unroll
        for (int c = 0; c < NC; c++) {
            float s0 = upk_sum(acc0[c]);
            float s1 = upk_sum(acc1[c]);
            float keep = (lane < 16) ? s0 : s1;
            float give = (lane < 16) ? s1 : s0;
            v[c] = keep + __shfl_xor_sync(0xffffffffu, give, 16);
        }
#pragma unroll
        for (int c = 0; c < NC; c++) {
#pragma unroll
            for (int off = 8; off; off >>= 1)
                v[c] += __shfl_xor_sync(0xffffffffu, v[c], off);
        }

        // two-lane parallel epilogue (lane 0 = word0, lane 16 = word1)
        if (lane == 0 || (lane == 16 && act1)) {
            int   w   = (lane == 0) ? w0 : w1;
            int   len = (lane == 0) ? len0 : len1;
            float inv = 1.0f / (float)len;
            float lg[NC];
            float m = -1e30f; int am = 0;
#pragma unroll
            for (int c = 0; c < NC; c++) {
                lg[c] = fmaf(v[c], inv, sb[c]);
                if (lg[c] > m) { m = lg[c]; am = c; }
            }
            out[1 + w] = (float)am;
            float sum = 0.0f;
#pragma unroll
            for (int c = 0; c < NC; c++) sum += __expf(lg[c] - m);
            int lab = label_ids[w];
            lab = lab < 0 ? 0 : (lab > NC - 1 ? NC - 1 : lab);
            lloss += -(lg[lab] - m - __logf(sum));
            lcnt  += 1;
        }

        p = pn; wp = wpn; lsa = lsan; lsb = lsbn;
    }

    // merge lane16 partials into lane0, then block/global reduce
    lloss += __shfl_xor_sync(0xffffffffu, lloss, 16);
    lcnt  += __shfl_xor_sync(0xffffffffu, lcnt,  16);
    if (lane == 0 && lcnt > 0) {
        atomicAdd(&s_loss, lloss);
        atomicAdd(&s_cnt, lcnt);
    }
    __syncthreads();

    if (tid == 0) {
        if (s_cnt > 0) {
            atomicAdd(&g_loss, s_loss);
            atomicAdd(&g_cnt, s_cnt);
        }
        __threadfence();
        int old = atomicAdd(&g_done, 1);
        if (old == MGRID - 1) {
            float lv = atomicAdd(&g_loss, 0.0f);
            int   cv = atomicAdd(&g_cnt, 0);
            out[0] = lv / fmaxf((float)cv, 1.0f);
            // self-clean for next graph replay
            g_loss = 0.0f; g_cnt = 0;
            atomicExch(&g_done, 0);
        }
    }
}

extern "C" void kernel_launch(void* const* d_in, const int* in_sizes, int n_in,
                              void* d_out, int out_size) {
    const float* bert_out  = (const float*)d_in[0];
    const float* W         = (const float*)d_in[1];
    const float* b         = (const float*)d_in[2];
    const int*   ids_lens  = (const int*)d_in[4];
    const int*   label_ids = (const int*)d_in[5];
    float* out = (float*)d_out;

    setup_kernel<<<BATCH, 256>>>(ids_lens, W, b, out);
    main_kernel<<<MGRID, 256>>>(bert_out, b, label_ids, out);
}